// round 11
// baseline (speedup 1.0000x reference)
#include <cuda_runtime.h>
#include <cstdint>

// ---------------------------------------------------------------------------
// AllPassMORRCirculantConv2d  (B=8, Cin=32, H=W=64, K=3, S=1, P=1, Cout=64)
// out[p*8+k] = sum_q (scale[q]*D) * rcp(K2 - 2AR*cos(phase_{p,q,k}))
// phase_{p,q,k} = sum_j inten[q*8+j] * w[p][q][(k-j)&7]   (circular conv n=8)
//
// R10: occupancy push. Channel-split staging (16 ch/phase -> smem 44.5KB,
//      4 blocks/SM) + __launch_bounds__(256,4) (regs<=64 -> 32 warps/SM).
//      Tail reverted to all-MUFU cos (R8 showed MUFU not binding).
// ---------------------------------------------------------------------------

#define AA 0.8578
#define RR 0.8985

static constexpr float G2f  = (float)(2.0 * AA * RR);                   // 2AR
static constexpr float K2f  = (float)(1.0 + (AA * RR) * (AA * RR));     // 1+(AR)^2
static constexpr float Df   = (float)((AA * AA + RR * RR) - 1.0
                                      - (AA * RR) * (AA * RR));         // K1-K2
static constexpr float GAINf = 1.6666666666666667f;                     // sqrt(100/36)

#define PH 66
#define PW 66
#define NPAD (8 * 32 * PH * PW)

// smem tile geometry: 16 channels x 3 rows x 65 pair-columns
#define TCH   16
#define TROWW 65
#define TSZ   (TCH * 3 * TROWW)      // 3120 float2 = 24960 B

typedef unsigned long long ull;

// Pre-shifted packed image: g_sq2[i] = { s[i], s[i+1] }, s = padded x^2*gain
__device__ float2 g_sq2[NPAD];

// ---------------- packed f32x2 helpers -------------------------------------
__device__ __forceinline__ ull pack2(float lo, float hi) {
    ull r;
    asm("mov.b64 %0, {%1, %2};" : "=l"(r) : "f"(lo), "f"(hi));
    return r;
}
__device__ __forceinline__ void unpack2(ull v, float& lo, float& hi) {
    asm("mov.b64 {%0, %1}, %2;" : "=f"(lo), "=f"(hi) : "l"(v));
}
__device__ __forceinline__ ull fma2(ull a, ull b, ull c) {
    ull d;
    asm("fma.rn.f32x2 %0, %1, %2, %3;" : "=l"(d) : "l"(a), "l"(b), "l"(c));
    return d;
}

// ---------------- Kernel 1: pad + square + gain + shift-pack ---------------
__device__ __forceinline__ float pad_val(const float* __restrict__ x, int j) {
    int px = j % PW;
    int t  = j / PW;
    int py = t % PH;
    int bc = t / PH;
    if (px >= 1 && px <= 64 && py >= 1 && py <= 64) {
        float u = x[bc * 4096 + (py - 1) * 64 + (px - 1)];
        return u * u * GAINf;
    }
    return 0.0f;
}

__global__ void prep_kernel(const float* __restrict__ x) {
    int i = blockIdx.x * blockDim.x + threadIdx.x;
    if (i >= NPAD) return;
    float v0 = pad_val(x, i);
    float v1 = (i + 1 < NPAD) ? pad_val(x, i + 1) : 0.0f;
    g_sq2[i] = make_float2(v0, v1);
}

// ---------------- Kernel 2: main -------------------------------------------
// block = 256 threads = 8 p-warps x 32 pixel-pairs (one row). grid = 512.
// Two phases: channels 0..15 <-> q 0..17, channels 16..31 <-> q 18..35.
__global__ __launch_bounds__(256, 4)
void morr_main_kernel(const float* __restrict__ weight,   // [8][36][8]
                      const float* __restrict__ mscale,   // [19]
                      float* __restrict__ out)            // [8][64][64][64]
{
    __shared__ float2   sp[TSZ];         // staged window pairs: 24960 B
    __shared__ ull      sww[8 * 36 * 8]; // {w,w} duplicated:    18432 B
    __shared__ float    ss2[36];         // scale[q] * D
    __shared__ unsigned stab[144];       // BYTE offsets (per-phase taps)

    const int tid = threadIdx.x;
    const int b   = blockIdx.x >> 6;       // image
    const int y   = blockIdx.x & 63;       // row

    for (int i = tid; i < 2304; i += 256) {
        float wv = weight[i];
        sww[i] = pack2(wv, wv);
    }
    if (tid < 36) {
        float s = (tid < 18) ? mscale[tid] : -mscale[tid - 18];
        ss2[tid] = s * Df;
    }
    if (tid < 144) {
        int c = tid / 9, r = tid % 9;      // c = channel local to phase
        stab[tid] = (unsigned)((((c * 3 + r / 3) * TROWW) + (r % 3)) * 8);
    }

    const int lane = tid & 31;
    const int p    = tid >> 5;             // warp index = output block p
    const int x    = lane * 2;             // even pixel of the pair

    const char* spx   = reinterpret_cast<const char*>(sp) + x * 8;
    const ull*  wbase = sww + p * 288;
    const float2* gsrc = g_sq2 + (b * 32) * (PH * PW) + y * PW;

    // acc[k] : pixel x ; acc[8+k] : pixel x+1   (channel p*8+k)
    float acc[16];
#pragma unroll
    for (int i = 0; i < 16; i++) acc[i] = 0.0f;

#pragma unroll 1
    for (int half = 0; half < 2; half++) {
        __syncthreads();                       // prior phase reads done
        // stage 16 channels x 3 rows x 65 pair-cols
        const float2* g0 = gsrc + (half * TCH) * (PH * PW);
        for (int i = tid; i < TSZ; i += 256) {
            int c   = i / (3 * TROWW);
            int rem = i - c * (3 * TROWW);
            int rr  = rem / TROWW;
            int pc  = rem - rr * TROWW;
            sp[i] = g0[(c * PH + rr) * PW + pc];
        }
        __syncthreads();

#pragma unroll 1
        for (int ql = 0; ql < 18; ql++) {
            const int q = half * 18 + ql;

            ull inten2[8];
#pragma unroll
            for (int t = 0; t < 8; t++)
                inten2[t] = *reinterpret_cast<const ull*>(spx + stab[ql * 8 + t]);

            ull w2[8];
#pragma unroll
            for (int m = 0; m < 8; m++) w2[m] = wbase[q * 8 + m];

            ull ph2[8] = {0ull, 0ull, 0ull, 0ull, 0ull, 0ull, 0ull, 0ull};
#pragma unroll
            for (int j = 0; j < 8; j++) {
#pragma unroll
                for (int k = 0; k < 8; k++)
                    ph2[k] = fma2(inten2[j], w2[(k - j) & 7], ph2[k]);
            }

            const float s2 = ss2[q];
#pragma unroll
            for (int k = 0; k < 8; k++) {
                float p0, p1;
                unpack2(ph2[k], p0, p1);
                float c0 = __cosf(p0);
                float c1 = __cosf(p1);
                float d0 = fmaf(-G2f, c0, K2f);
                float d1 = fmaf(-G2f, c1, K2f);
                float r0, r1;
                asm("rcp.approx.f32 %0, %1;" : "=f"(r0) : "f"(d0));
                asm("rcp.approx.f32 %0, %1;" : "=f"(r1) : "f"(d1));
                acc[k]     = fmaf(s2, r0, acc[k]);
                acc[8 + k] = fmaf(s2, r1, acc[8 + k]);
            }
        }
    }

    float* op = out + (b * 64 + p * 8) * 4096 + y * 64 + x;
#pragma unroll
    for (int k = 0; k < 8; k++)
        *reinterpret_cast<float2*>(op + k * 4096) = make_float2(acc[k], acc[8 + k]);
}

// ---------------- launch ----------------------------------------------------
extern "C" void kernel_launch(void* const* d_in, const int* in_sizes, int n_in,
                              void* d_out, int out_size)
{
    const float* x   = (const float*)d_in[0];   // (8,32,64,64)
    const float* wgt = (const float*)d_in[1];   // (8,36,8)
    const float* ms  = (const float*)d_in[2];   // (19,)
    float* out = (float*)d_out;                 // (8,64,64,64)

    prep_kernel<<<(NPAD + 255) / 256, 256>>>(x);
    morr_main_kernel<<<512, 256>>>(wgt, ms, out);
}

// round 12
// speedup vs baseline: 1.0811x; 1.0811x over previous
#include <cuda_runtime.h>
#include <cstdint>

// ---------------------------------------------------------------------------
// AllPassMORRCirculantConv2d  (B=8, Cin=32, H=W=64, K=3, S=1, P=1, Cout=64)
// out[p*8+k] = sum_q (scale[q]*D) * rcp(K2 - 2AR*cos(phase_{p,q,k}))
// phase_{p,q,k} = sum_j inten[q*8+j] * w[p][q][(k-j)&7]   (circular conv n=8)
//
// R11: instruction-count cut. 9 q's = 72 taps = exactly 8 channels, so the
//      q-loop unrolls in groups of 9 with ALL tap/weight/scale offsets as
//      compile-time immediates (no stab[] LDS, no address IMAD/IADD3), and
//      full cross-q ILP. Reg cap back to 85 (R10's 64-reg cap spilled).
// ---------------------------------------------------------------------------

#define AA 0.8578
#define RR 0.8985

static constexpr float G2f  = (float)(2.0 * AA * RR);                   // 2AR
static constexpr float K2f  = (float)(1.0 + (AA * RR) * (AA * RR));     // 1+(AR)^2
static constexpr float Df   = (float)((AA * AA + RR * RR) - 1.0
                                      - (AA * RR) * (AA * RR));         // K1-K2
static constexpr float GAINf = 1.6666666666666667f;                     // sqrt(100/36)

#define PH 66
#define PW 66
#define NPAD (8 * 32 * PH * PW)

// smem tile geometry: 16 channels x 3 rows x 65 pair-columns (per phase)
#define TCH   16
#define TROWW 65
#define TSZ   (TCH * 3 * TROWW)      // 3120 float2 = 24960 B
#define CH_STRIDE_B (3 * TROWW * 8)  // bytes per channel in tile

typedef unsigned long long ull;

// Pre-shifted packed image: g_sq2[i] = { s[i], s[i+1] }, s = padded x^2*gain
__device__ float2 g_sq2[NPAD];

// ---------------- packed f32x2 helpers -------------------------------------
__device__ __forceinline__ ull pack2(float lo, float hi) {
    ull r;
    asm("mov.b64 %0, {%1, %2};" : "=l"(r) : "f"(lo), "f"(hi));
    return r;
}
__device__ __forceinline__ void unpack2(ull v, float& lo, float& hi) {
    asm("mov.b64 {%0, %1}, %2;" : "=f"(lo), "=f"(hi) : "l"(v));
}
__device__ __forceinline__ ull fma2(ull a, ull b, ull c) {
    ull d;
    asm("fma.rn.f32x2 %0, %1, %2, %3;" : "=l"(d) : "l"(a), "l"(b), "l"(c));
    return d;
}

// ---------------- Kernel 1: pad + square + gain + shift-pack ---------------
__device__ __forceinline__ float pad_val(const float* __restrict__ x, int j) {
    int px = j % PW;
    int t  = j / PW;
    int py = t % PH;
    int bc = t / PH;
    if (px >= 1 && px <= 64 && py >= 1 && py <= 64) {
        float u = x[bc * 4096 + (py - 1) * 64 + (px - 1)];
        return u * u * GAINf;
    }
    return 0.0f;
}

__global__ void prep_kernel(const float* __restrict__ x) {
    int i = blockIdx.x * blockDim.x + threadIdx.x;
    if (i >= NPAD) return;
    float v0 = pad_val(x, i);
    float v1 = (i + 1 < NPAD) ? pad_val(x, i + 1) : 0.0f;
    g_sq2[i] = make_float2(v0, v1);
}

// ---------------- Kernel 2: main -------------------------------------------
// block = 256 threads = 8 p-warps x 32 pixel-pairs (one row). grid = 512.
// q structure: 2 halves (16 ch each) x 2 groups (9 q = 8 ch) fully unrolled.
__global__ __launch_bounds__(256, 3)
void morr_main_kernel(const float* __restrict__ weight,   // [8][36][8]
                      const float* __restrict__ mscale,   // [19]
                      float* __restrict__ out)            // [8][64][64][64]
{
    __shared__ float2 sp[TSZ];           // staged window pairs: 24960 B
    __shared__ ull    sww[8 * 36 * 8];   // {w,w} duplicated:    18432 B
    __shared__ float  ss2[36];           // scale[q] * D

    const int tid = threadIdx.x;
    const int b   = blockIdx.x >> 6;       // image
    const int y   = blockIdx.x & 63;       // row

    for (int i = tid; i < 2304; i += 256) {
        float wv = weight[i];
        sww[i] = pack2(wv, wv);
    }
    if (tid < 36) {
        float s = (tid < 18) ? mscale[tid] : -mscale[tid - 18];
        ss2[tid] = s * Df;
    }

    const int lane = tid & 31;
    const int p    = tid >> 5;             // warp index = output block p
    const int x    = lane * 2;             // even pixel of the pair

    const char*   spx  = reinterpret_cast<const char*>(sp) + x * 8;
    const float2* gsrc = g_sq2 + (b * 32) * (PH * PW) + y * PW;

    // acc[k] : pixel x ; acc[8+k] : pixel x+1   (channel p*8+k)
    float acc[16];
#pragma unroll
    for (int i = 0; i < 16; i++) acc[i] = 0.0f;

#pragma unroll 1
    for (int half = 0; half < 2; half++) {
        __syncthreads();                   // prior phase reads done
        const float2* g0 = gsrc + (half * TCH) * (PH * PW);
        for (int i = tid; i < TSZ; i += 256) {
            int c   = i / (3 * TROWW);
            int rem = i - c * (3 * TROWW);
            int rr  = rem / TROWW;
            int pc  = rem - rr * TROWW;
            sp[i] = g0[(c * PH + rr) * PW + pc];
        }
        __syncthreads();

#pragma unroll 1
        for (int grp = 0; grp < 2; grp++) {
            // channels (local) grp*8 .. grp*8+7 ; q = half*18 + grp*9 + ql
            const char* cbase = spx + grp * 8 * CH_STRIDE_B;
            const int   qbase = half * 18 + grp * 9;
            const ull*  wq    = sww + p * 288 + qbase * 8;

#pragma unroll
            for (int ql = 0; ql < 9; ql++) {
                ull inten2[8];
#pragma unroll
                for (int t = 0; t < 8; t++) {
                    const int w  = ql * 8 + t;        // 0..71 within group
                    const int c  = w / 9;             // compile-time
                    const int r  = w % 9;
                    const int off = (c * 3 + r / 3) * TROWW * 8 + (r % 3) * 8;
                    inten2[t] = *reinterpret_cast<const ull*>(cbase + off);
                }

                ull w2[8];
#pragma unroll
                for (int m = 0; m < 8; m++) w2[m] = wq[ql * 8 + m];

                ull ph2[8] = {0ull, 0ull, 0ull, 0ull, 0ull, 0ull, 0ull, 0ull};
#pragma unroll
                for (int j = 0; j < 8; j++) {
#pragma unroll
                    for (int k = 0; k < 8; k++)
                        ph2[k] = fma2(inten2[j], w2[(k - j) & 7], ph2[k]);
                }

                const float s2 = ss2[qbase + ql];
#pragma unroll
                for (int k = 0; k < 8; k++) {
                    float p0, p1;
                    unpack2(ph2[k], p0, p1);
                    float c0 = __cosf(p0);
                    float c1 = __cosf(p1);
                    float d0 = fmaf(-G2f, c0, K2f);
                    float d1 = fmaf(-G2f, c1, K2f);
                    float r0, r1;
                    asm("rcp.approx.f32 %0, %1;" : "=f"(r0) : "f"(d0));
                    asm("rcp.approx.f32 %0, %1;" : "=f"(r1) : "f"(d1));
                    acc[k]     = fmaf(s2, r0, acc[k]);
                    acc[8 + k] = fmaf(s2, r1, acc[8 + k]);
                }
            }
        }
    }

    float* op = out + (b * 64 + p * 8) * 4096 + y * 64 + x;
#pragma unroll
    for (int k = 0; k < 8; k++)
        *reinterpret_cast<float2*>(op + k * 4096) = make_float2(acc[k], acc[8 + k]);
}

// ---------------- launch ----------------------------------------------------
extern "C" void kernel_launch(void* const* d_in, const int* in_sizes, int n_in,
                              void* d_out, int out_size)
{
    const float* x   = (const float*)d_in[0];   // (8,32,64,64)
    const float* wgt = (const float*)d_in[1];   // (8,36,8)
    const float* ms  = (const float*)d_in[2];   // (19,)
    float* out = (float*)d_out;                 // (8,64,64,64)

    prep_kernel<<<(NPAD + 255) / 256, 256>>>(x);
    morr_main_kernel<<<512, 256>>>(wgt, ms, out);
}